// round 17
// baseline (speedup 1.0000x reference)
#include <cuda_runtime.h>
#include <cuda_fp16.h>
#include <cstdint>

#define BATCH 2048
#define MF    26
#define KE    32
#define C1    (MF*MF)
#define NPAIR 351
#define NTRI  3276
#define NJ    3328
#define OUTW  256
#define NKS   8

typedef unsigned long long ull;

__device__ int    g_e2pqj[NTRI];
__device__ float  g_W1s[384 * 128];       // [pq][i]; row 351 = b1, 352.. = 0
__device__ float  g_W2t[NJ * 128];        // [i][j*128+h], i-row stride NJ
__device__ float  g_U[352 * NJ];          // [pq][j*128+h]; row 351 = v
__device__ __half g_W1h[128 * 384];       // W1s^T hi [i][pq]
__device__ __half g_W1l[128 * 384];
__device__ __half g_TFh[BATCH * 384];     // G-vector hi [b][e]
__device__ __half g_TFl[BATCH * 384];
__device__ __half g_Th[BATCH * NJ];       // T hi [b][e]
__device__ __half g_Tl[BATCH * NJ];
__device__ __half g_Uh[128 * NJ];         // Up^T hi [h][e]
__device__ __half g_Ul[128 * NJ];
__device__ float  g_P[NKS * BATCH * 128];

#define FMA2(a, x, y) asm("fma.rn.f32x2 %0, %1, %2, %0;" : "+l"(a) : "l"(x), "l"(y))
#define MUL2(d, x, y) asm("mul.rn.f32x2 %0, %1, %2;" : "=l"(d) : "l"(x), "l"(y))
#define ADD2(a, x)    asm("add.rn.f32x2 %0, %0, %1;" : "+l"(a) : "l"(x))
#define DUP2(d, f)    asm("mov.b64 %0, {%1, %1};" : "=l"(d) : "f"(f))

__device__ __forceinline__ unsigned sptr(const void* p) {
    return (unsigned)__cvta_generic_to_shared(p);
}
__device__ __forceinline__ void cp16(unsigned s, const void* g) {
    asm volatile("cp.async.cg.shared.global [%0], [%1], 16;\n" :: "r"(s), "l"(g));
}
#define CP_COMMIT() asm volatile("cp.async.commit_group;\n" ::)
#define CP_WAIT0()  asm volatile("cp.async.wait_group 0;\n" ::)
#define CP_WAIT1()  asm volatile("cp.async.wait_group 1;\n" ::)

#define LDSM4(r0, r1, r2, r3, addr) \
    asm volatile("ldmatrix.sync.aligned.m8n8.x4.shared.b16 {%0,%1,%2,%3}, [%4];" \
        : "=r"(r0), "=r"(r1), "=r"(r2), "=r"(r3) : "r"(addr))
#define MMA16816(d, a, b) \
    asm volatile("mma.sync.aligned.m16n8k16.row.col.f32.f16.f16.f32 " \
        "{%0,%1,%2,%3}, {%4,%5,%6,%7}, {%8,%9}, {%0,%1,%2,%3};" \
        : "+f"((d)[0]), "+f"((d)[1]), "+f"((d)[2]), "+f"((d)[3]) \
        : "r"((a)[0]), "r"((a)[1]), "r"((a)[2]), "r"((a)[3]), "r"((b)[0]), "r"((b)[1]))

__device__ __forceinline__ int pq_off(int p) { return p * MF - (p * (p - 1)) / 2; }

__device__ __forceinline__ void pq_decode(int pq, int& p, int& q) {
    p = (int)(26.5f - sqrtf(702.25f - 2.0f * (float)pq));
    if (p < 0) p = 0;
    while (p > 0 && pq_off(p) > pq) p--;
    while (pq_off(p + 1) <= pq) p++;
    q = p + (pq - pq_off(p));
}

// ---------------------------------------------------------------------------
// kA_prep: [0,416) W2 transpose; [416,608) W1s (+fp16 transposed); [608,621) e2pqj
// ---------------------------------------------------------------------------
__global__ __launch_bounds__(256) void kA_prep(
    const float* __restrict__ W1, const float* __restrict__ b1,
    const float* __restrict__ W2)
{
    const int bx = blockIdx.x;
    const int t  = threadIdx.x;
    if (bx < 416) {
        __shared__ float tile[32][33];
        int c0 = (bx % 104) * 32;
        int h0 = (bx / 104) * 32;
        int tx = t & 31, ty = t >> 5;
#pragma unroll
        for (int r = 0; r < 4; r++)
            tile[ty + 8 * r][tx] = W2[(size_t)(h0 + ty + 8 * r) * NJ + c0 + tx];
        __syncthreads();
#pragma unroll
        for (int r = 0; r < 4; r++)
            g_W2t[(size_t)(c0 + ty + 8 * r) * 128 + h0 + tx] = tile[tx][ty + 8 * r];
    } else if (bx < 608) {
        int idx = (bx - 416) * 256 + t;
        int pq = idx >> 7, i = idx & 127;
        float v = 0.f;
        if (pq == NPAIR) v = b1[i];
        else if (pq < NPAIR) {
            int p, q; pq_decode(pq, p, q);
            v = W1[i * C1 + p * MF + q];
            if (p < q) v += W1[i * C1 + q * MF + p];
        }
        g_W1s[idx] = v;
        __half hi = __float2half_rn(v);
        g_W1h[(size_t)i * 384 + pq] = hi;
        g_W1l[(size_t)i * 384 + pq] = __float2half_rn(v - __half2float(hi));
    } else {
        int e = (bx - 608) * 256 + t;
        if (e < NTRI) {
            int rem = e, p = 0;
            while (rem >= (MF - p) * (MF - p + 1) / 2) { rem -= (MF - p) * (MF - p + 1) / 2; p++; }
            int q = p;
            while (rem >= MF - q) { rem -= MF - q; q++; }
            g_e2pqj[e] = p | (q << 8) | ((q + rem) << 16);
        }
    }
}

// ---------------------------------------------------------------------------
// k_feat v3 (fixed): per-batch features via HMMA.
//   A rows indexed by I-MAJOR pq (matching e2pqj / epilogue); row 351 = ones.
//   D[pq][j]=T, D[pq][26]=G, D[351][j]=sx, D[351][26]=32.
// ---------------------------------------------------------------------------
#define FO_A   3744
#define FO_AL  26272
#define FO_B   48800
#define FO_BL  50848
#define FO_D   52896
#define FEAT_SMEM 100768   // FO_D + 352*34*4

__global__ __launch_bounds__(384, 2) void k_feat(const float* __restrict__ x0g) {
    extern __shared__ __align__(16) char fs[];
    ull (*xsr)[18] = reinterpret_cast<ull(*)[18]>(fs);     // [26][18]
    float (*sD)[34] = reinterpret_cast<float(*)[34]>(fs + FO_D);
    const uint32_t sb = sptr(fs);
    const int b = blockIdx.x;
    const int t = threadIdx.x;
    const int w = t >> 5, lane = t & 31;

    // load x0
    for (int idx = t; idx < MF * 16; idx += 384) {
        int j = idx >> 4, kp = idx & 15;
        xsr[j][kp] = *reinterpret_cast<const ull*>(
            x0g + (size_t)b * (MF * KE) + j * KE + 2 * kp);
    }
    __syncthreads();

    // stage B [32 j][32 k] fp16 hi/lo (j<26: x0; j==26: ones; else 0)
    for (int idx = t; idx < 1024; idx += 384) {
        int j = idx >> 5, k = idx & 31;
        float v = (j < MF) ? reinterpret_cast<const float*>(&xsr[j][0])[k]
                           : (j == MF ? 1.0f : 0.0f);
        __half hh = __float2half_rn(v);
        __half hl = __float2half_rn(v - __half2float(hh));
        uint32_t off = (uint32_t)(j * 64 + ((((k >> 3) ^ (j & 3)) << 4) | ((k & 7) * 2)));
        *reinterpret_cast<__half*>(fs + FO_B + off)  = hh;
        *reinterpret_cast<__half*>(fs + FO_BL + off) = hl;
    }

    // xx rows, I-MAJOR pq index (row 351 = ones)
    if (w < 11) {
        int pq = w * 32 + lane;
        const bool ones = (pq >= NPAIR);
        int p = 0, q = 0;
        if (!ones) pq_decode(pq, p, q);
        char* rowH = fs + FO_A  + pq * 64;
        char* rowL = fs + FO_AL + pq * 64;
#pragma unroll
        for (int kp = 0; kp < 16; kp++) {
            float2 f;
            if (ones) { f.x = 1.0f; f.y = 1.0f; }
            else {
                ull m; MUL2(m, xsr[p][kp], xsr[q][kp]);
                f = *reinterpret_cast<float2*>(&m);
            }
            __half h0 = __float2half_rn(f.x), h1 = __float2half_rn(f.y);
            uint32_t o = (uint32_t)(((((kp >> 2) ^ (pq & 3)) << 4)) | ((kp & 3) * 4));
            *reinterpret_cast<__half2*>(rowH + o) = __halves2half2(h0, h1);
            *reinterpret_cast<__half2*>(rowL + o) = __halves2half2(
                __float2half_rn(f.x - __half2float(h0)),
                __float2half_rn(f.y - __half2float(h1)));
        }
    }
    __syncthreads();

    // MMA: m-tiles 0..21 (16 rows each), n = 32 (4 frags), k = 32 (2 steps)
    const int aRowOff = lane & 15;
    const uint32_t aColX = (uint32_t)((lane >> 4) << 4);
    const int bRow4 = (lane & 7) + ((lane >> 4) << 3);
    const uint32_t bCol4 = (uint32_t)(((lane >> 3) & 1) << 4);
    const int g = lane >> 2, tq = lane & 3;

#pragma unroll
    for (int mi = 0; mi < 2; mi++) {
        int mt = w + 12 * mi;
        if (mt >= 22) break;
        float d[4][4];
#pragma unroll
        for (int nf = 0; nf < 4; nf++)
#pragma unroll
            for (int e = 0; e < 4; e++) d[nf][e] = 0.f;

#pragma unroll
        for (int k16 = 0; k16 < 2; k16++) {
            uint32_t ah[4], al[4], bh[4][2], bl[4][2];
            {
                int row = mt * 16 + aRowOff;
                uint32_t colb = (uint32_t)(k16 * 32) + aColX;
                uint32_t addr = sb + FO_A + (uint32_t)(row * 64)
                              + (colb ^ ((uint32_t)(row & 3) << 4));
                LDSM4(ah[0], ah[1], ah[2], ah[3], addr);
                LDSM4(al[0], al[1], al[2], al[3], addr + (FO_AL - FO_A));
            }
#pragma unroll
            for (int p2 = 0; p2 < 2; p2++) {
                int row = 16 * p2 + bRow4;
                uint32_t colb = (uint32_t)(k16 * 32) + bCol4;
                uint32_t addr = sb + FO_B + (uint32_t)(row * 64)
                              + (colb ^ ((uint32_t)(row & 3) << 4));
                LDSM4(bh[2 * p2][0], bh[2 * p2][1], bh[2 * p2 + 1][0], bh[2 * p2 + 1][1], addr);
                LDSM4(bl[2 * p2][0], bl[2 * p2][1], bl[2 * p2 + 1][0], bl[2 * p2 + 1][1],
                      addr + (FO_BL - FO_B));
            }
#pragma unroll
            for (int nf = 0; nf < 4; nf++) {
                MMA16816(d[nf], ah, bh[nf]);
                MMA16816(d[nf], ah, bl[nf]);
                MMA16816(d[nf], al, bh[nf]);
            }
        }
#pragma unroll
        for (int nf = 0; nf < 4; nf++) {
            int col = 8 * nf + 2 * tq;
            *reinterpret_cast<float2*>(&sD[mt * 16 + g][col])     = make_float2(d[nf][0], d[nf][1]);
            *reinterpret_cast<float2*>(&sD[mt * 16 + g + 8][col]) = make_float2(d[nf][2], d[nf][3]);
        }
    }
    __syncthreads();

    // G-vector fp16 hi/lo [b][384]  (sD rows are i-major pq)
    if (t < 192) {
        int e = 2 * t;
        float v0 = (e < NPAIR) ? sD[e][26] : (e == NPAIR ? 32.0f : 0.0f);
        float v1 = (e + 1 < NPAIR) ? sD[e + 1][26] : (e + 1 == NPAIR ? 32.0f : 0.0f);
        __half h0 = __float2half_rn(v0), h1 = __float2half_rn(v1);
        size_t o = (size_t)b * 384 + e;
        *reinterpret_cast<__half2*>(&g_TFh[o]) = __halves2half2(h0, h1);
        *reinterpret_cast<__half2*>(&g_TFl[o]) = __halves2half2(
            __float2half_rn(v0 - __half2float(h0)),
            __float2half_rn(v1 - __half2float(h1)));
    }

    // T-vector fp16 hi/lo [b][3328]
    for (int e2 = t; e2 < NJ / 2; e2 += 384) {
        int e = 2 * e2;
        float v0, v1;
        if (e + 1 < NTRI) {
            int2 c2 = *reinterpret_cast<const int2*>(g_e2pqj + e);
            int p0 = c2.x & 255, q0 = (c2.x >> 8) & 255, j0 = (c2.x >> 16) & 255;
            int p1 = c2.y & 255, q1 = (c2.y >> 8) & 255, j1 = (c2.y >> 16) & 255;
            v0 = sD[pq_off(p0) + q0 - p0][j0];
            v1 = sD[pq_off(p1) + q1 - p1][j1];
        } else {
#pragma unroll
            for (int u = 0; u < 2; u++) {
                int ee = e + u;
                float v;
                if (ee < NTRI) {
                    int c = g_e2pqj[ee];
                    int p = c & 255, q = (c >> 8) & 255, j = (c >> 16) & 255;
                    v = sD[pq_off(p) + q - p][j];
                } else if (ee < NTRI + MF) v = sD[NPAIR][ee - NTRI];
                else if (ee == NTRI + MF)  v = 32.0f;
                else                       v = 0.0f;
                if (u == 0) v0 = v; else v1 = v;
            }
        }
        __half h0 = __float2half_rn(v0), h1 = __float2half_rn(v1);
        size_t o = (size_t)b * NJ + e;
        *reinterpret_cast<__half2*>(&g_Th[o]) = __halves2half2(h0, h1);
        *reinterpret_cast<__half2*>(&g_Tl[o]) = __halves2half2(
            __float2half_rn(v0 - __half2float(h0)),
            __float2half_rn(v1 - __half2float(h1)));
    }
}

// ---------------------------------------------------------------------------
// k_u: U = W1s @ W2t. 48m x 128n tiles, grid 208, 384 thr.
// ---------------------------------------------------------------------------
__global__ __launch_bounds__(384) void k_u() {
    __shared__ float As[32][52];
    __shared__ float Bs[32][132];
    const int t = threadIdx.x;
    int m0 = (blockIdx.x & 7) * 48;
    int n0 = (blockIdx.x >> 3) * 128;
    const int tx = t & 31, ty = t >> 5;

    ull acc[4][2];
#pragma unroll
    for (int r = 0; r < 4; r++) { acc[r][0] = 0ULL; acc[r][1] = 0ULL; }

    for (int kc = 0; kc < 128; kc += 32) {
        __syncthreads();
        {
            int row = t >> 3, c4 = t & 7;
            float4 v = *reinterpret_cast<const float4*>(
                g_W1s + (size_t)(m0 + row) * 128 + kc + 4 * c4);
            As[4 * c4 + 0][row] = v.x;
            As[4 * c4 + 1][row] = v.y;
            As[4 * c4 + 2][row] = v.z;
            As[4 * c4 + 3][row] = v.w;
        }
#pragma unroll
        for (int l = 0; l < 3; l++) {
            int idx = t + 384 * l;
            if (idx < 1024) {
                int row = idx >> 5, c4 = idx & 31;
                *reinterpret_cast<float4*>(&Bs[row][4 * c4]) =
                    *reinterpret_cast<const float4*>(g_W2t + (size_t)(kc + row) * NJ + n0 + 4 * c4);
            }
        }
        __syncthreads();

#pragma unroll
        for (int kk = 0; kk < 32; kk++) {
            float4 a = *reinterpret_cast<const float4*>(&As[kk][4 * ty]);
            ulonglong2 wv = *reinterpret_cast<const ulonglong2*>(&Bs[kk][4 * tx]);
            ull d;
            DUP2(d, a.x); FMA2(acc[0][0], wv.x, d); FMA2(acc[0][1], wv.y, d);
            DUP2(d, a.y); FMA2(acc[1][0], wv.x, d); FMA2(acc[1][1], wv.y, d);
            DUP2(d, a.z); FMA2(acc[2][0], wv.x, d); FMA2(acc[2][1], wv.y, d);
            DUP2(d, a.w); FMA2(acc[3][0], wv.x, d); FMA2(acc[3][1], wv.y, d);
        }
    }
#pragma unroll
    for (int r = 0; r < 4; r++) {
        int m = m0 + 4 * ty + r;
        if (m < 352) {
            float* dst = g_U + (size_t)m * NJ + n0 + 4 * tx;
            *reinterpret_cast<float2*>(dst)     = *reinterpret_cast<float2*>(&acc[r][0]);
            *reinterpret_cast<float2*>(dst + 2) = *reinterpret_cast<float2*>(&acc[r][1]);
        }
    }
}

// ---------------------------------------------------------------------------
// k_fold: grid (52,4) — 64e x 32h tiles, warp-uniform e reads, smem
//   transpose, e-coalesced fp16 writes.
// ---------------------------------------------------------------------------
__global__ __launch_bounds__(256) void k_fold(const float* __restrict__ b2) {
    __shared__ float tile[64][33];
    const int t  = threadIdx.x;
    const int e0 = blockIdx.x * 64;
    const int h0 = blockIdx.y * 32;
    const int hl = t & 31;
    const int h  = h0 + hl;
    const int er = t >> 5;

#pragma unroll
    for (int i = 0; i < 8; i++) {
        int el = er + 8 * i;
        int e = e0 + el;
        float val = 0.f;
        if (e < NTRI) {
            int c = g_e2pqj[e];
            int p = c & 255, q = (c >> 8) & 255, j = (c >> 16) & 255;
            #define CU(PQ, J) g_U[(size_t)(PQ) * NJ + (J) * 128 + h]
            if (p < q) {
                if (q < j) val = CU(pq_off(p) + q - p, j) + CU(pq_off(p) + j - p, q) + CU(pq_off(q) + j - q, p);
                else       val = CU(pq_off(p) + q - p, q) + CU(pq_off(q), p);
            } else {
                if (q < j) val = CU(pq_off(p), j) + CU(pq_off(p) + j - p, p);
                else       val = CU(pq_off(p), p);
            }
            #undef CU
        } else if (e < NTRI + MF) {
            val = g_U[(size_t)NPAIR * NJ + (e - NTRI) * 128 + h];
        } else if (e == NTRI + MF) {
            val = b2[h];
        }
        tile[el][hl] = val;
    }
    __syncthreads();

#pragma unroll
    for (int i = 0; i < 8; i++) {
        int idx = t + 256 * i;
        int h2 = idx >> 6;
        int el = idx & 63;
        float val = tile[el][h2];
        __half hi = __float2half_rn(val);
        float lo = val - __half2float(hi);
        size_t o = (size_t)(h0 + h2) * NJ + e0 + el;
        g_Uh[o] = hi;
        g_Ul[o] = __float2half_rn(lo);
    }
}

// ---------------------------------------------------------------------------
// k_tc: grid 288 (single wave at 2 CTAs/SM), all HMMA, dyn smem 96K.
// ---------------------------------------------------------------------------
#define STAGE_BYTES 49152
__global__ __launch_bounds__(256) void k_tc(float* __restrict__ out) {
    extern __shared__ __align__(16) char dyn[];
    const int t = threadIdx.x;
    const int id = blockIdx.x;
    const int wid = t >> 5, lane = t & 31;
    const int wm = wid >> 2, wn = wid & 3;
    const int mr0 = 32 * wm, nr0 = 32 * wn;

    const __half *Ah, *Al, *Bh, *Bl;
    int astr, bstr, nch, kbase, b0;
    float* dst;
    int dstr;
    if (id < 256) {
        int bt = id >> 3, ks = id & 7;
        b0 = bt * 64;
        Ah = g_Th; Al = g_Tl; Bh = g_Uh; Bl = g_Ul;
        astr = NJ; bstr = NJ;
        nch = (ks < 4) ? 7 : 6;
        kbase = 64 * ((ks < 4) ? 7 * ks : 28 + 6 * (ks - 4));
        dst = g_P + (size_t)ks * BATCH * 128;
        dstr = 128;
    } else {
        b0 = (id - 256) * 64;
        Ah = g_TFh; Al = g_TFl; Bh = g_W1h; Bl = g_W1l;
        astr = 384; bstr = 384;
        nch = 6; kbase = 0;
        dst = out;
        dstr = OUTW;
    }

    const uint32_t sBase = sptr(dyn);

    float d[2][4][4];
#pragma unroll
    for (int mf = 0; mf < 2; mf++)
#pragma unroll
        for (int nf = 0; nf < 4; nf++)
#pragma unroll
            for (int e = 0; e < 4; e++) d[mf][nf][e] = 0.f;

    const int aR = t >> 3, aC = t & 7;
    const uint32_t aSw0 = (uint32_t)(aR * 128 + ((aC ^ (aR & 7)) << 4));
    const int aR1 = (t + 256) >> 3;
    const uint32_t aSw1 = (uint32_t)(aR1 * 128 + ((aC ^ (aR1 & 7)) << 4));

    const int aRowOff = lane & 15;
    const uint32_t aColX = (uint32_t)((lane >> 4) << 4);
    const int bRow4 = (lane & 7) + ((lane >> 4) << 3);
    const uint32_t bCol4 = (uint32_t)(((lane >> 3) & 1) << 4);

    auto stage_issue = [&](int ch) {
        const int kc = kbase + ch * 64;
        const uint32_t sb = sBase + (uint32_t)(ch & 1) * STAGE_BYTES;
        {
            size_t go0 = (size_t)(b0 + aR) * astr + kc + aC * 8;
            size_t go1 = (size_t)(b0 + aR1) * astr + kc + aC * 8;
            cp16(sb + aSw0,        Ah + go0);
            cp16(sb + 8192 + aSw0, Al + go0);
            cp16(sb + aSw1,        Ah + go1);
            cp16(sb + 8192 + aSw1, Al + go1);
        }
#pragma unroll
        for (int i = 0; i < 4; i++) {
            int u = t + 256 * i;
            int r = u >> 3, c8 = u & 7;
            uint32_t sw = (uint32_t)(r * 128 + ((c8 ^ (r & 7)) << 4));
            size_t go = (size_t)r * bstr + kc + c8 * 8;
            cp16(sb + 16384 + sw, Bh + go);
            cp16(sb + 32768 + sw, Bl + go);
        }
        CP_COMMIT();
    };

    stage_issue(0);
    if (nch > 1) stage_issue(1);

    for (int ch = 0; ch < nch; ch++) {
        if (ch + 1 < nch) { CP_WAIT1(); } else { CP_WAIT0(); }
        __syncthreads();

        const uint32_t sb = sBase + (uint32_t)(ch & 1) * STAGE_BYTES;
        const uint32_t sA = sb, sB = sb + 16384;

#pragma unroll
        for (int k16 = 0; k16 < 4; k16++) {
            uint32_t ah[2][4], al[2][4], bhf[4][2], blf[4][2];
#pragma unroll
            for (int mf = 0; mf < 2; mf++) {
                int row = mr0 + 16 * mf + aRowOff;
                uint32_t colb = (uint32_t)(k16 * 32) + aColX;
                uint32_t addr = sA + (uint32_t)(row * 128) + (colb ^ ((uint32_t)(row & 7) << 4));
                LDSM4(ah[mf][0], ah[mf][1], ah[mf][2], ah[mf][3], addr);
                LDSM4(al[mf][0], al[mf][1], al[mf][2], al[mf][3], addr + 8192);
            }
#pragma unroll
            for (int p2 = 0; p2 < 2; p2++) {
                int row = nr0 + 16 * p2 + bRow4;
                uint32_t colb = (uint32_t)(k16 * 32) + bCol4;
                uint32_t addr = sB + (uint32_t)(row * 128) + (colb ^ ((uint32_t)(row & 7) << 4));
                LDSM4(bhf[2 * p2][0], bhf[2 * p2][1], bhf[2 * p2 + 1][0], bhf[2 * p2 + 1][1], addr);
                LDSM4(blf[2 * p2][0], blf[2 * p2][1], blf[2 * p2 + 1][0], blf[2 * p2 + 1][1], addr + 16384);
            }
#pragma unroll
            for (int mf = 0; mf < 2; mf++)
#pragma unroll
                for (int nf = 0; nf < 4; nf++) {
                    MMA16816(d[mf][nf], ah[mf], bhf[nf]);
                    MMA16816(d[mf][nf], ah[mf], blf[nf]);
                    MMA16816(d[mf][nf], al[mf], bhf[nf]);
                }
        }

        __syncthreads();
        if (ch + 2 < nch) stage_issue(ch + 2);
    }

    const int g = lane >> 2, tq = lane & 3;
#pragma unroll
    for (int mf = 0; mf < 2; mf++) {
        int rbase = b0 + mr0 + 16 * mf;
#pragma unroll
        for (int nf = 0; nf < 4; nf++) {
            int h = nr0 + 8 * nf + 2 * tq;
            *reinterpret_cast<float2*>(dst + (size_t)(rbase + g) * dstr + h) =
                make_float2(d[mf][nf][0], d[mf][nf][1]);
            *reinterpret_cast<float2*>(dst + (size_t)(rbase + g + 8) * dstr + h) =
                make_float2(d[mf][nf][2], d[mf][nf][3]);
        }
    }
}

// ---------------------------------------------------------------------------
// k_red: out[:,128:256] = sum of 8 partials
// ---------------------------------------------------------------------------
__global__ void k_red(float* __restrict__ out) {
    int gid = blockIdx.x * blockDim.x + threadIdx.x;
    int b = gid >> 7, h = gid & 127;
    const int N = BATCH * 128;
    float s0 = g_P[gid]         + g_P[gid + N];
    float s1 = g_P[gid + 2 * N] + g_P[gid + 3 * N];
    float s2 = g_P[gid + 4 * N] + g_P[gid + 5 * N];
    float s3 = g_P[gid + 6 * N] + g_P[gid + 7 * N];
    out[(size_t)b * OUTW + 128 + h] = (s0 + s1) + (s2 + s3);
}

// ---------------------------------------------------------------------------
// launch: two-stream graph (weight chain hidden under feat).
// ---------------------------------------------------------------------------
extern "C" void kernel_launch(void* const* d_in, const int* in_sizes, int n_in,
                              void* d_out, int out_size) {
    const float* inputs = (const float*)d_in[0];
    const float* W1     = (const float*)d_in[1];
    const float* b1     = (const float*)d_in[2];
    const float* W2     = (const float*)d_in[3];
    const float* b2     = (const float*)d_in[4];
    float* out = (float*)d_out;

    cudaFuncSetAttribute(k_tc, cudaFuncAttributeMaxDynamicSharedMemorySize, 2 * STAGE_BYTES);
    cudaFuncSetAttribute(k_feat, cudaFuncAttributeMaxDynamicSharedMemorySize, FEAT_SMEM);

    cudaStream_t s2;
    cudaStreamCreateWithFlags(&s2, cudaStreamNonBlocking);
    cudaEvent_t evFork, evJoin;
    cudaEventCreateWithFlags(&evFork, cudaEventDisableTiming);
    cudaEventCreateWithFlags(&evJoin, cudaEventDisableTiming);

    cudaEventRecord(evFork, 0);
    cudaStreamWaitEvent(s2, evFork, 0);

    kA_prep<<<621, 256, 0, s2>>>(W1, b1, W2);
    k_u<<<208, 384, 0, s2>>>();
    k_fold<<<dim3(52, 4), 256, 0, s2>>>(b2);
    cudaEventRecord(evJoin, s2);

    k_feat<<<BATCH, 384, FEAT_SMEM>>>(inputs);

    cudaStreamWaitEvent(0, evJoin, 0);
    k_tc<<<288, 256, 2 * STAGE_BYTES>>>(out);
    k_red<<<(BATCH * 128) / 256, 256>>>(out);

    cudaEventDestroy(evFork);
    cudaEventDestroy(evJoin);
    cudaStreamDestroy(s2);
}